// round 2
// baseline (speedup 1.0000x reference)
#include <cuda_runtime.h>
#include <math.h>

#define BB 8
#define LL 64
#define DD 1024
#define NNs 128
#define RRs 64
#define MM (BB*LL)   // 512

// Scratch (allocation-free: device globals)
__device__ float g_xp[MM*DD];     // pre-activation proj output
__device__ float g_xone[MM*DD];   // conv+silu output
__device__ float g_dbc[MM*(RRs+2*NNs)]; // 512 x 320
__device__ float g_delta[MM*DD];
__device__ float g_u[MM*DD];      // gated output before final proj

// ---------------------------------------------------------------------------
// Generic NT GEMM: C[m,n] = sum_k A[m*lda+k] * B[n*ldb+k] (+bias[n]) (+act)
// M, N multiples of 64; K multiple of 32. BM=BN=64, BK=32, 256 thr, 4x4/thr.
// ACT: 0=none, 1=softplus
// ---------------------------------------------------------------------------
template<int ACT, bool BIAS>
__global__ __launch_bounds__(256) void gemm_nt(
    const float* __restrict__ A, int lda,
    const float* __restrict__ B, int ldb,
    const float* __restrict__ bias,
    float* __restrict__ C, int ldc,
    int K)
{
    __shared__ __align__(16) float As[32][68];
    __shared__ __align__(16) float Bs[32][68];

    const int tid = threadIdx.x;
    const int mBase = blockIdx.y * 64;
    const int nBase = blockIdx.x * 64;
    const int tx = tid & 15;          // n sub-tile
    const int ty = tid >> 4;          // m sub-tile

    float c[4][4];
#pragma unroll
    for (int i = 0; i < 4; i++)
#pragma unroll
        for (int j = 0; j < 4; j++) c[i][j] = 0.f;

    const float* Ap = A + (size_t)mBase * lda;
    const float* Bp = B + (size_t)nBase * ldb;

    for (int k0 = 0; k0 < K; k0 += 32) {
#pragma unroll
        for (int r = 0; r < 8; r++) {
            int idx = tid + r * 256;          // 2048 elems
            int m = idx >> 5, k = idx & 31;
            As[k][m] = Ap[(size_t)m * lda + k0 + k];
            Bs[k][m] = Bp[(size_t)m * ldb + k0 + k];
        }
        __syncthreads();
#pragma unroll
        for (int k = 0; k < 32; k++) {
            float4 av = *(const float4*)&As[k][ty * 4];
            float4 bv = *(const float4*)&Bs[k][tx * 4];
            float ar[4] = {av.x, av.y, av.z, av.w};
            float br[4] = {bv.x, bv.y, bv.z, bv.w};
#pragma unroll
            for (int i = 0; i < 4; i++)
#pragma unroll
                for (int j = 0; j < 4; j++)
                    c[i][j] = fmaf(ar[i], br[j], c[i][j]);
        }
        __syncthreads();
    }

#pragma unroll
    for (int i = 0; i < 4; i++) {
        int m = mBase + ty * 4 + i;
#pragma unroll
        for (int j = 0; j < 4; j++) {
            int n = nBase + tx * 4 + j;
            float v = c[i][j];
            if (BIAS) v += bias[n];
            if (ACT == 1) {
                // stable softplus
                v = fmaxf(v, 0.f) + log1pf(__expf(-fabsf(v)));
            }
            C[(size_t)m * ldc + n] = v;
        }
    }
}

// ---------------------------------------------------------------------------
// Conv over feature axis, seq treated as channels, k=3, pad 1, then SiLU.
// out[b,o,h] = silu( sum_{i,k} xp[b,i,h+k-1]*w[o,i,k] + cb[o] )
// grid: (hChunk 16, oHalf 2, b 8); block 256. Each block: 32 o x 64 h.
// ---------------------------------------------------------------------------
__global__ __launch_bounds__(256) void conv_silu_kernel(
    const float* __restrict__ xp, const float* __restrict__ conv_w,
    const float* __restrict__ conv_b, float* __restrict__ xone)
{
    __shared__ float s_w[3][32][64];   // [k][o_local][i]  24 KB
    __shared__ float s_x[64][66];      // [i][h-halo]      16.9 KB

    const int tid = threadIdx.x;
    const int h0 = blockIdx.x * 64;
    const int oBase = blockIdx.y * 32;
    const int b = blockIdx.z;

#pragma unroll
    for (int r = 0; r < 24; r++) {          // 3*32*64 = 6144
        int idx = tid + r * 256;
        int o = idx / 192, rem = idx % 192;
        int i = rem / 3, k = rem % 3;
        s_w[k][o][i] = conv_w[(oBase + o) * 192 + rem];
    }
#pragma unroll
    for (int r = 0; r < 17; r++) {          // 64*66 = 4224
        int idx = tid + r * 256;
        if (idx < 64 * 66) {
            int i = idx / 66, cc = idx % 66;
            int g = h0 - 1 + cc;
            s_x[i][cc] = (g >= 0 && g < DD)
                         ? xp[((size_t)b * LL + i) * DD + g] : 0.f;
        }
    }
    __syncthreads();

    const int h = tid & 63;
    const int o0 = tid >> 6;   // 0..3

    float acc[8];
#pragma unroll
    for (int jj = 0; jj < 8; jj++) acc[jj] = conv_b[oBase + o0 + 4 * jj];

    for (int i = 0; i < 64; i++) {
        float x0 = s_x[i][h];
        float x1 = s_x[i][h + 1];
        float x2 = s_x[i][h + 2];
#pragma unroll
        for (int jj = 0; jj < 8; jj++) {
            int o = o0 + 4 * jj;
            acc[jj] = fmaf(s_w[0][o][i], x0, acc[jj]);
            acc[jj] = fmaf(s_w[1][o][i], x1, acc[jj]);
            acc[jj] = fmaf(s_w[2][o][i], x2, acc[jj]);
        }
    }
#pragma unroll
    for (int jj = 0; jj < 8; jj++) {
        int o = oBase + o0 + 4 * jj;
        float v = acc[jj];
        v = v / (1.f + __expf(-v));       // silu
        xone[((size_t)b * LL + o) * DD + h0 + h] = v;
    }
}

// ---------------------------------------------------------------------------
// Fused SSM: selective scan + C-dot + D-skip + gate(silu(xp)) + residual.
// One warp per (b, e). N=128 -> 4 states/lane. L=64 sequential recurrence.
// u[b,l,e] = (y[b,l,e] + Dp[e]*xone) * silu(xp[b,l,e]) + x[b,l,e]
// ---------------------------------------------------------------------------
__global__ __launch_bounds__(256) void ssm_scan_kernel(
    const float* __restrict__ delta, const float* __restrict__ xone,
    const float* __restrict__ dbc,   const float* __restrict__ A_log,
    const float* __restrict__ Dp,    const float* __restrict__ xp,
    const float* __restrict__ xin,   float* __restrict__ u)
{
    const int warp = (blockIdx.x * blockDim.x + threadIdx.x) >> 5;
    const int lane = threadIdx.x & 31;
    const int b = warp >> 10;        // / 1024
    const int e = warp & 1023;

    float a[4], h[4];
#pragma unroll
    for (int j = 0; j < 4; j++) {
        a[j] = -__expf(A_log[e * NNs + lane + 32 * j]);
        h[j] = 0.f;
    }
    const float dpe = Dp[e];

    for (int l = 0; l < 64; l++) {
        size_t idx = ((size_t)(b * 64 + l)) * DD + e;
        float dlt = delta[idx];
        float xv  = xone[idx];
        const float* row = dbc + (size_t)(b * 64 + l) * 320;

        float acc = 0.f;
#pragma unroll
        for (int j = 0; j < 4; j++) {
            float Bv = row[64 + lane + 32 * j];
            float Cv = row[192 + lane + 32 * j];
            float dA = __expf(dlt * a[j]);
            h[j] = fmaf(dA, h[j], dlt * Bv * xv);
            acc  = fmaf(h[j], Cv, acc);
        }
#pragma unroll
        for (int off = 16; off; off >>= 1)
            acc += __shfl_xor_sync(0xffffffffu, acc, off);

        if (lane == 0) {
            float xpv = xp[idx];
            float xt  = xpv / (1.f + __expf(-xpv));   // silu -> x_two
            float y   = acc + dpe * xv;
            u[idx] = fmaf(y, xt, xin[idx]);           // gate + residual skip
        }
    }
}

// ---------------------------------------------------------------------------
extern "C" void kernel_launch(void* const* d_in, const int* in_sizes, int n_in,
                              void* d_out, int out_size)
{
    const float* x      = (const float*)d_in[0];
    const float* proj_w = (const float*)d_in[1];
    const float* proj_b = (const float*)d_in[2];
    const float* conv_w = (const float*)d_in[3];
    const float* conv_b = (const float*)d_in[4];
    const float* dbc_w  = (const float*)d_in[5];
    const float* dt_w   = (const float*)d_in[6];
    const float* dt_b   = (const float*)d_in[7];
    const float* A_log  = (const float*)d_in[8];
    const float* Dp     = (const float*)d_in[9];
    float* out = (float*)d_out;

    float *xp, *xone, *dbcb, *delta, *u;
    cudaGetSymbolAddress((void**)&xp,    g_xp);
    cudaGetSymbolAddress((void**)&xone,  g_xone);
    cudaGetSymbolAddress((void**)&dbcb,  g_dbc);
    cudaGetSymbolAddress((void**)&delta, g_delta);
    cudaGetSymbolAddress((void**)&u,     g_u);

    // 1) xp = x @ proj_w^T + proj_b            (512x1024, K=1024)
    gemm_nt<0, true><<<dim3(16, 8), 256>>>(x, DD, proj_w, DD, proj_b, xp, DD, DD);

    // 2) x_one = silu(conv(xp) + conv_b)
    conv_silu_kernel<<<dim3(16, 2, 8), 256>>>(xp, conv_w, conv_b, xone);

    // 3) dbc = x_one @ dbc_w^T                 (512x320, K=1024)
    gemm_nt<0, false><<<dim3(5, 8), 256>>>(xone, DD, dbc_w, DD, nullptr, dbcb, 320, DD);

    // 4) delta = softplus(dbc[:, :64] @ dt_w^T + dt_b)   (512x1024, K=64)
    gemm_nt<1, true><<<dim3(16, 8), 256>>>(dbcb, 320, dt_w, RRs, dt_b, delta, DD, RRs);

    // 5) fused scan + gate + skip -> u
    ssm_scan_kernel<<<1024, 256>>>(delta, xone, dbcb, A_log, Dp, xp, x, u);

    // 6) out = u @ proj_w^T + proj_b
    gemm_nt<0, true><<<dim3(16, 8), 256>>>(u, DD, proj_w, DD, proj_b, out, DD, DD);
}

// round 12
// speedup vs baseline: 1.2844x; 1.2844x over previous
#include <cuda_runtime.h>
#include <math.h>

#define BB 8
#define LL 64
#define DD 1024
#define NNs 128
#define RRs 64
#define MM (BB*LL)   // 512

// Scratch (allocation-free: device globals)
__device__ float g_xp[MM*DD];             // pre-activation proj output
__device__ float g_xone[MM*DD];           // conv+silu output
__device__ float g_dbc[MM*(RRs+2*NNs)];   // 512 x 320
__device__ float g_delta[MM*DD];
__device__ float g_u[MM*DD];              // gated output before final proj
__device__ float g_part[4*MM*DD];         // split-K partials (max 4*512*1024 = 8MB)

// ---------------------------------------------------------------------------
// Split-K NT GEMM: part[z][m,n] = sum_{k in slice z} A[m,k]*B[n,k]
// Tile: BM=128, BN=64, BK=32. 256 threads, 8x4 per thread.
// Double-buffered smem, register prefetch, conflict-free STS.
// grid = (N/64, M/128, S); Kslice = K/S (multiple of 32).
// ---------------------------------------------------------------------------
__global__ __launch_bounds__(256) void gemm_splitk(
    const float* __restrict__ A, int lda,
    const float* __restrict__ B, int ldb,
    float* __restrict__ part, int N,
    int Kslice, int MN)
{
    __shared__ __align__(16) float sA[2][32*132];  // [k][m], stride 132
    __shared__ __align__(16) float sB[2][32*68];   // [k][n], stride 68

    const int tid  = threadIdx.x;
    const int lane = tid & 31;
    const int warp = tid >> 5;
    const int tx = tid & 15;           // n: 4 cols
    const int ty = tid >> 4;           // m: 8 rows
    const int mBase = blockIdx.y * 128;
    const int nBase = blockIdx.x * 64;
    const int kOff0 = blockIdx.z * Kslice;

    // lane->element mapping (conflict-free STS into [k][m] layout):
    // k = (lane&7) + 8*(r&3); m = (lane>>3) + 4*warp + 32*(r>>2)
    const int kl = lane & 7;
    const int mlw = (lane >> 3) + (warp << 2);

    const float* Ap = A + (size_t)mBase * lda;
    const float* Bp = B + (size_t)nBase * ldb;

    float ra[16], rb[8];
    const int nkb = Kslice >> 5;

    // ---- prologue: load k-block 0 ----
    {
        int k0 = kOff0;
#pragma unroll
        for (int r = 0; r < 16; r++) {
            int k = kl + ((r & 3) << 3);
            int m = mlw + ((r >> 2) << 5);
            ra[r] = Ap[(size_t)m * lda + k0 + k];
        }
#pragma unroll
        for (int r = 0; r < 8; r++) {
            int k = kl + ((r & 3) << 3);
            int m = mlw + ((r >> 2) << 5);
            rb[r] = Bp[(size_t)m * ldb + k0 + k];
        }
#pragma unroll
        for (int r = 0; r < 16; r++) {
            int k = kl + ((r & 3) << 3);
            int m = mlw + ((r >> 2) << 5);
            sA[0][k * 132 + m] = ra[r];
        }
#pragma unroll
        for (int r = 0; r < 8; r++) {
            int k = kl + ((r & 3) << 3);
            int m = mlw + ((r >> 2) << 5);
            sB[0][k * 68 + m] = rb[r];
        }
    }
    __syncthreads();

    float c[8][4];
#pragma unroll
    for (int i = 0; i < 8; i++)
#pragma unroll
        for (int j = 0; j < 4; j++) c[i][j] = 0.f;

    for (int kb = 0; kb < nkb; kb++) {
        const int cur = kb & 1;
        const bool hasNext = (kb + 1 < nkb);
        if (hasNext) {
            int k0 = kOff0 + (kb + 1) * 32;
#pragma unroll
            for (int r = 0; r < 16; r++) {
                int k = kl + ((r & 3) << 3);
                int m = mlw + ((r >> 2) << 5);
                ra[r] = Ap[(size_t)m * lda + k0 + k];
            }
#pragma unroll
            for (int r = 0; r < 8; r++) {
                int k = kl + ((r & 3) << 3);
                int m = mlw + ((r >> 2) << 5);
                rb[r] = Bp[(size_t)m * ldb + k0 + k];
            }
        }

        const float* bufA = sA[cur];
        const float* bufB = sB[cur];
#pragma unroll 8
        for (int k = 0; k < 32; k++) {
            float4 a0 = *(const float4*)&bufA[k * 132 + ty * 8];
            float4 a1 = *(const float4*)&bufA[k * 132 + ty * 8 + 4];
            float4 bv = *(const float4*)&bufB[k * 68 + tx * 4];
            float ar[8] = {a0.x, a0.y, a0.z, a0.w, a1.x, a1.y, a1.z, a1.w};
            float br[4] = {bv.x, bv.y, bv.z, bv.w};
#pragma unroll
            for (int i = 0; i < 8; i++)
#pragma unroll
                for (int j = 0; j < 4; j++)
                    c[i][j] = fmaf(ar[i], br[j], c[i][j]);
        }

        if (hasNext) {
            const int nxt = cur ^ 1;
#pragma unroll
            for (int r = 0; r < 16; r++) {
                int k = kl + ((r & 3) << 3);
                int m = mlw + ((r >> 2) << 5);
                sA[nxt][k * 132 + m] = ra[r];
            }
#pragma unroll
            for (int r = 0; r < 8; r++) {
                int k = kl + ((r & 3) << 3);
                int m = mlw + ((r >> 2) << 5);
                sB[nxt][k * 68 + m] = rb[r];
            }
            __syncthreads();
        }
    }

    // ---- epilogue: write partials ----
    float* Cp = part + (size_t)blockIdx.z * MN;
#pragma unroll
    for (int i = 0; i < 8; i++) {
        int m = mBase + ty * 8 + i;
        float4 v = make_float4(c[i][0], c[i][1], c[i][2], c[i][3]);
        *(float4*)&Cp[(size_t)m * N + nBase + tx * 4] = v;
    }
}

// ---------------------------------------------------------------------------
// Split-K reduce + bias + activation. ACT: 0=none, 1=softplus.
// One float4 per thread.
// ---------------------------------------------------------------------------
template<int ACT, bool BIAS>
__global__ __launch_bounds__(256) void reduce_k(
    const float* __restrict__ part, int MN, int S,
    const float* __restrict__ bias,
    float* __restrict__ C, int N)
{
    int i4 = blockIdx.x * 256 + threadIdx.x;
    int MN4 = MN >> 2;
    if (i4 >= MN4) return;

    const float4* p4 = (const float4*)part;
    float4 acc = p4[i4];
    for (int s = 1; s < S; s++) {
        float4 v = p4[(size_t)s * MN4 + i4];
        acc.x += v.x; acc.y += v.y; acc.z += v.z; acc.w += v.w;
    }
    if (BIAS) {
        int n = (i4 << 2) % N;
        float4 bv = *(const float4*)&bias[n];
        acc.x += bv.x; acc.y += bv.y; acc.z += bv.z; acc.w += bv.w;
    }
    if (ACT == 1) {
        acc.x = fmaxf(acc.x, 0.f) + log1pf(__expf(-fabsf(acc.x)));
        acc.y = fmaxf(acc.y, 0.f) + log1pf(__expf(-fabsf(acc.y)));
        acc.z = fmaxf(acc.z, 0.f) + log1pf(__expf(-fabsf(acc.z)));
        acc.w = fmaxf(acc.w, 0.f) + log1pf(__expf(-fabsf(acc.w)));
    }
    ((float4*)C)[i4] = acc;
}

// ---------------------------------------------------------------------------
// Conv over feature axis, seq treated as channels, k=3, pad 1, then SiLU.
// ---------------------------------------------------------------------------
__global__ __launch_bounds__(256) void conv_silu_kernel(
    const float* __restrict__ xp, const float* __restrict__ conv_w,
    const float* __restrict__ conv_b, float* __restrict__ xone)
{
    __shared__ float s_w[3][32][64];   // [k][o_local][i]
    __shared__ float s_x[64][66];      // [i][h-halo]

    const int tid = threadIdx.x;
    const int h0 = blockIdx.x * 64;
    const int oBase = blockIdx.y * 32;
    const int b = blockIdx.z;

#pragma unroll
    for (int r = 0; r < 24; r++) {
        int idx = tid + r * 256;
        int o = idx / 192, rem = idx % 192;
        int i = rem / 3, k = rem % 3;
        s_w[k][o][i] = conv_w[(oBase + o) * 192 + rem];
    }
#pragma unroll
    for (int r = 0; r < 17; r++) {
        int idx = tid + r * 256;
        if (idx < 64 * 66) {
            int i = idx / 66, cc = idx % 66;
            int g = h0 - 1 + cc;
            s_x[i][cc] = (g >= 0 && g < DD)
                         ? xp[((size_t)b * LL + i) * DD + g] : 0.f;
        }
    }
    __syncthreads();

    const int h = tid & 63;
    const int o0 = tid >> 6;

    float acc[8];
#pragma unroll
    for (int jj = 0; jj < 8; jj++) acc[jj] = conv_b[oBase + o0 + 4 * jj];

    for (int i = 0; i < 64; i++) {
        float x0 = s_x[i][h];
        float x1 = s_x[i][h + 1];
        float x2 = s_x[i][h + 2];
#pragma unroll
        for (int jj = 0; jj < 8; jj++) {
            int o = o0 + 4 * jj;
            acc[jj] = fmaf(s_w[0][o][i], x0, acc[jj]);
            acc[jj] = fmaf(s_w[1][o][i], x1, acc[jj]);
            acc[jj] = fmaf(s_w[2][o][i], x2, acc[jj]);
        }
    }
#pragma unroll
    for (int jj = 0; jj < 8; jj++) {
        int o = oBase + o0 + 4 * jj;
        float v = acc[jj];
        v = v / (1.f + __expf(-v));       // silu
        xone[((size_t)b * LL + o) * DD + h0 + h] = v;
    }
}

// ---------------------------------------------------------------------------
// Fused SSM: selective scan + C-dot + D-skip + gate(silu(xp)) + residual.
// One warp per (b, e). N=128 -> 4 states/lane. L=64 sequential recurrence.
// ---------------------------------------------------------------------------
__global__ __launch_bounds__(256) void ssm_scan_kernel(
    const float* __restrict__ delta, const float* __restrict__ xone,
    const float* __restrict__ dbc,   const float* __restrict__ A_log,
    const float* __restrict__ Dp,    const float* __restrict__ xp,
    const float* __restrict__ xin,   float* __restrict__ u)
{
    const int warp = (blockIdx.x * blockDim.x + threadIdx.x) >> 5;
    const int lane = threadIdx.x & 31;
    const int b = warp >> 10;
    const int e = warp & 1023;

    float a[4], h[4];
#pragma unroll
    for (int j = 0; j < 4; j++) {
        a[j] = -__expf(A_log[e * NNs + lane + 32 * j]);
        h[j] = 0.f;
    }
    const float dpe = Dp[e];

    for (int l = 0; l < 64; l++) {
        size_t idx = ((size_t)(b * 64 + l)) * DD + e;
        float dlt = delta[idx];
        float xv  = xone[idx];
        const float* row = dbc + (size_t)(b * 64 + l) * 320;

        float acc = 0.f;
#pragma unroll
        for (int j = 0; j < 4; j++) {
            float Bv = row[64 + lane + 32 * j];
            float Cv = row[192 + lane + 32 * j];
            float dA = __expf(dlt * a[j]);
            h[j] = fmaf(dA, h[j], dlt * Bv * xv);
            acc  = fmaf(h[j], Cv, acc);
        }
#pragma unroll
        for (int off = 16; off; off >>= 1)
            acc += __shfl_xor_sync(0xffffffffu, acc, off);

        if (lane == 0) {
            float xpv = xp[idx];
            float xt  = xpv / (1.f + __expf(-xpv));   // silu -> x_two
            float y   = acc + dpe * xv;
            u[idx] = fmaf(y, xt, xin[idx]);           // gate + residual skip
        }
    }
}

// ---------------------------------------------------------------------------
extern "C" void kernel_launch(void* const* d_in, const int* in_sizes, int n_in,
                              void* d_out, int out_size)
{
    const float* x      = (const float*)d_in[0];
    const float* proj_w = (const float*)d_in[1];
    const float* proj_b = (const float*)d_in[2];
    const float* conv_w = (const float*)d_in[3];
    const float* conv_b = (const float*)d_in[4];
    const float* dbc_w  = (const float*)d_in[5];
    const float* dt_w   = (const float*)d_in[6];
    const float* dt_b   = (const float*)d_in[7];
    const float* A_log  = (const float*)d_in[8];
    const float* Dp     = (const float*)d_in[9];
    float* out = (float*)d_out;

    float *xp, *xone, *dbcb, *delta, *u, *part;
    cudaGetSymbolAddress((void**)&xp,    g_xp);
    cudaGetSymbolAddress((void**)&xone,  g_xone);
    cudaGetSymbolAddress((void**)&dbcb,  g_dbc);
    cudaGetSymbolAddress((void**)&delta, g_delta);
    cudaGetSymbolAddress((void**)&u,     g_u);
    cudaGetSymbolAddress((void**)&part,  g_part);

    const int MN_proj = MM * DD;       // 524288
    const int MN_dbc  = MM * 320;      // 163840

    // 1) xp = x @ proj_w^T + proj_b     (512x1024, K=1024, S=4)
    gemm_splitk<<<dim3(16, 4, 4), 256>>>(x, DD, proj_w, DD, part, DD, 256, MN_proj);
    reduce_k<0, true><<<512, 256>>>(part, MN_proj, 4, proj_b, xp, DD);

    // 2) x_one = silu(conv(xp) + conv_b)
    conv_silu_kernel<<<dim3(16, 2, 8), 256>>>(xp, conv_w, conv_b, xone);

    // 3) dbc = x_one @ dbc_w^T          (512x320, K=1024, S=8)
    gemm_splitk<<<dim3(5, 4, 8), 256>>>(xone, DD, dbc_w, DD, part, 320, 128, MN_dbc);
    reduce_k<0, false><<<160, 256>>>(part, MN_dbc, 8, nullptr, dbcb, 320);

    // 4) delta = softplus(dbc[:, :64] @ dt_w^T + dt_b)   (512x1024, K=64, S=2)
    gemm_splitk<<<dim3(16, 4, 2), 256>>>(dbcb, 320, dt_w, RRs, part, DD, 32, MN_proj);
    reduce_k<1, true><<<512, 256>>>(part, MN_proj, 2, dt_b, delta, DD);

    // 5) fused scan + gate + skip -> u
    ssm_scan_kernel<<<1024, 256>>>(delta, xone, dbcb, A_log, Dp, xp, x, u);

    // 6) out = u @ proj_w^T + proj_b    (S=4)
    gemm_splitk<<<dim3(16, 4, 4), 256>>>(u, DD, proj_w, DD, part, DD, 256, MN_proj);
    reduce_k<0, true><<<512, 256>>>(part, MN_proj, 4, proj_b, out, DD);
}